// round 4
// baseline (speedup 1.0000x reference)
#include <cuda_runtime.h>

#define HID 512
#define NHEAD 8
#define DHEAD 64
#define NB 8
#define MQ 512
#define LW 1024
#define SKV 1536
#define SCALEF 0.125f

typedef unsigned long long u64;

// ---- packed f32x2 helpers (sm_100+): one FFMA2 = 2 FMAs per issue slot ----
__device__ __forceinline__ u64 pk2(float lo, float hi) {
  u64 r; asm("mov.b64 %0, {%1, %2};" : "=l"(r) : "f"(lo), "f"(hi)); return r;
}
__device__ __forceinline__ u64 bc2(float x) { return pk2(x, x); }
__device__ __forceinline__ u64 f2fma(u64 a, u64 b, u64 c) {
  u64 d; asm("fma.rn.f32x2 %0, %1, %2, %3;" : "=l"(d) : "l"(a), "l"(b), "l"(c));
  return d;
}
__device__ __forceinline__ u64 f2mul(u64 a, u64 b) {
  u64 d; asm("mul.rn.f32x2 %0, %1, %2;" : "=l"(d) : "l"(a), "l"(b)); return d;
}
__device__ __forceinline__ void upk(u64 v, float& lo, float& hi) {
  asm("mov.b64 {%0, %1}, %2;" : "=f"(lo), "=f"(hi) : "l"(v));
}

// ---------------- scratch (device globals: allocation-free rule) -----------
__device__ float g_Q[NB * MQ * HID];    // 8 MB
__device__ float g_K[NB * SKV * HID];   // 24 MB
__device__ float g_V[NB * SKV * HID];   // 24 MB
__device__ float g_AO[NB * MQ * HID];   // 8 MB

// ---------------- GEMM: Y[N,512] = X[N,512] @ W[512,512]^T -----------------
// 128x64 block tile, BK=16, 256 threads, 8x4 micro-tile (as 8x2 f32x2 pairs).
// W tile transposed in smem so B-operand is naturally packed (u64 loads);
// A-operand is a broadcast scalar packed once per (row,kk) on the ALU pipe.
__global__ __launch_bounds__(256) void gemm_xwt(const float* __restrict__ X,
                                                const float* __restrict__ W,
                                                float* __restrict__ Y) {
  __shared__ __align__(16) float Xs[128][17];
  __shared__ __align__(16) float WsT[16][68];
  const int t = threadIdx.x;
  const int n0 = blockIdx.x << 7;
  const int o0 = blockIdx.y << 6;
  const int row0 = (t >> 4) << 3;   // 0..120 (half-warp uniform -> broadcast)
  const int col0 = (t & 15) << 2;   // 0..60
  const int lr = t >> 2;            // 0..63
  const int lc = (t & 3) << 2;      // 0,4,8,12

  u64 acc2[8][2];
#pragma unroll
  for (int i = 0; i < 8; i++) { acc2[i][0] = 0ull; acc2[i][1] = 0ull; }

  for (int h0 = 0; h0 < HID; h0 += 16) {
#pragma unroll
    for (int i = 0; i < 2; i++) {
      int r = lr + (i << 6);
      float4 v = *(const float4*)(X + (size_t)(n0 + r) * HID + h0 + lc);
      Xs[r][lc + 0] = v.x; Xs[r][lc + 1] = v.y;
      Xs[r][lc + 2] = v.z; Xs[r][lc + 3] = v.w;
    }
    {
      float4 v = *(const float4*)(W + (size_t)(o0 + lr) * HID + h0 + lc);
      WsT[lc + 0][lr] = v.x; WsT[lc + 1][lr] = v.y;
      WsT[lc + 2][lr] = v.z; WsT[lc + 3][lr] = v.w;
    }
    __syncthreads();
#pragma unroll
    for (int kk = 0; kk < 16; kk++) {
      const u64* b2 = (const u64*)(&WsT[kk][col0]);   // 16B-aligned pair
      u64 b0 = b2[0], b1 = b2[1];
#pragma unroll
      for (int i = 0; i < 8; i++) {
        u64 a2 = bc2(Xs[row0 + i][kk]);
        acc2[i][0] = f2fma(a2, b0, acc2[i][0]);
        acc2[i][1] = f2fma(a2, b1, acc2[i][1]);
      }
    }
    __syncthreads();
  }
#pragma unroll
  for (int i = 0; i < 8; i++) {
    float4 v;
    upk(acc2[i][0], v.x, v.y);
    upk(acc2[i][1], v.z, v.w);
    *(float4*)(Y + (size_t)(n0 + row0 + i) * HID + o0 + col0) = v;
  }
}

// ---------------- fused sliding-window attention ---------------------------
// Block = one (batch,head) x 64 queries. 16 chunks of 64 relative positions.
// Per chunk: content scores as REGULAR 64x128 abs-coordinate GEMM (kst is the
// d-major transposed K band), positional scores as 64x64 GEMM, online softmax
// extracting the band sc[ti][ti+tj], probs written back in abs layout with
// complement zeroed, AV as regular 64x128x64 GEMM. Mask applied post-softmax:
// masked numerator, unmasked denominator. All GEMM loops use f32x2.
#define OFF_QS 0          /* [64][68]  */
#define OFF_PES 4352      /* [64][68]  */
#define OFF_KST 8704      /* [64][136] d-major K band */
#define OFF_VS 17408      /* [128][68] */
#define OFF_SP 26112      /* [64][68]  positional scores */
#define OFF_SC 30464      /* [64][136] content scores / probs (abs layout) */
#define OFF_RM 39168
#define OFF_RSUM 39232
#define OFF_RC 39296
#define SM_FLOATS 39360
#define SM_BYTES (SM_FLOATS * 4)

__global__ __launch_bounds__(256) void attn_kernel(
    const float* __restrict__ Q, const float* __restrict__ Kg,
    const float* __restrict__ Vg, const float* __restrict__ pe,
    const float* __restrict__ span, float* __restrict__ AO) {
  extern __shared__ __align__(16) float sm[];
  float* qs = sm + OFF_QS;
  float* pes = sm + OFF_PES;
  float* kst = sm + OFF_KST;
  float* vs = sm + OFF_VS;
  float* sp = sm + OFF_SP;
  float* sc = sm + OFF_SC;
  float* rm = sm + OFF_RM;
  float* rsum = sm + OFF_RSUM;
  float* rc = sm + OFF_RC;

  const int t = threadIdx.x;
  const int bh = blockIdx.y;
  const int b = bh >> 3, hd = bh & 7;
  const int i0 = blockIdx.x << 6;
  const float spanL = span[hd] * (float)LW;

  const float* Qb = Q + (size_t)(b * MQ + i0) * HID + hd * DHEAD;
  const float* Kb = Kg + (size_t)b * SKV * HID + hd * DHEAD;
  const float* Vb = Vg + (size_t)b * SKV * HID + hd * DHEAD;

  // q tile [64][64] -> qs (stride 68)
#pragma unroll
  for (int it = 0; it < 4; it++) {
    int idx = t + (it << 8);
    int r = idx >> 4, c = (idx & 15) << 2;
    *(float4*)(qs + r * 68 + c) = *(const float4*)(Qb + (size_t)r * HID + c);
  }
  if (t < 64) { rm[t] = -3.0e38f; rsum[t] = 0.f; rc[t] = 0.f; }

  u64 out2[4][2];   // 4 rows x (2 f32x2 pairs = 4 head-dims)
#pragma unroll
  for (int i = 0; i < 4; i++) { out2[i][0] = 0ull; out2[i][1] = 0ull; }

  const int r0 = (t >> 5) << 3;   // content rows (warp-uniform -> broadcast)
  const int a0 = (t & 31) << 2;   // content abs cols (conflict-free pairs)
  const int ti0 = (t >> 4) << 2;  // pos/AV rows
  const int tx0 = (t & 15) << 2;  // pos cols / AV d cols
  const int w = t >> 5, lane = t & 31;

  for (int ch = 0; ch < 16; ch++) {
    const int j0 = ch << 6;
    __syncthreads();  // previous chunk's readers done before overwrite

    // K band transposed -> kst[d][r], V band -> vs[r][d], pe chunk -> pes[d][tj]
    const float* Kband = Kb + (size_t)(i0 + j0) * HID;
    const float* Vband = Vb + (size_t)(i0 + j0) * HID;
#pragma unroll
    for (int it = 0; it < 8; it++) {
      int idx = t + (it << 8);
      int r = idx >> 4, c = (idx & 15) << 2;  // r in 0..127 (max key 1535, OK)
      float4 kv = *(const float4*)(Kband + (size_t)r * HID + c);
      kst[(c + 0) * 136 + r] = kv.x;
      kst[(c + 1) * 136 + r] = kv.y;
      kst[(c + 2) * 136 + r] = kv.z;
      kst[(c + 3) * 136 + r] = kv.w;
      *(float4*)(vs + r * 68 + c) = *(const float4*)(Vband + (size_t)r * HID + c);
    }
#pragma unroll
    for (int it = 0; it < 4; it++) {
      int idx = t + (it << 8);
      int d = idx >> 4, c = (idx & 15) << 2;
      *(float4*)(pes + d * 68 + c) = *(const float4*)(pe + (size_t)d * LW + j0 + c);
    }
    __syncthreads();

    // ---- phase A1: content scores sc[ti][a] = q_ti . k_band[a], 64x128 ----
    {
      u64 acc2[8][2];
#pragma unroll
      for (int i = 0; i < 8; i++) { acc2[i][0] = 0ull; acc2[i][1] = 0ull; }
#pragma unroll 2
      for (int d = 0; d < 64; d += 4) {
        ulonglong2 k0 = *(const ulonglong2*)(kst + (d + 0) * 136 + a0);
        ulonglong2 k1 = *(const ulonglong2*)(kst + (d + 1) * 136 + a0);
        ulonglong2 k2 = *(const ulonglong2*)(kst + (d + 2) * 136 + a0);
        ulonglong2 k3 = *(const ulonglong2*)(kst + (d + 3) * 136 + a0);
#pragma unroll
        for (int i = 0; i < 8; i++) {
          float4 qa = *(const float4*)(qs + (r0 + i) * 68 + d);
          u64 q0 = bc2(qa.x), q1 = bc2(qa.y), q2 = bc2(qa.z), q3 = bc2(qa.w);
          acc2[i][0] = f2fma(q3, k3.x, f2fma(q2, k2.x, f2fma(q1, k1.x, f2fma(q0, k0.x, acc2[i][0]))));
          acc2[i][1] = f2fma(q3, k3.y, f2fma(q2, k2.y, f2fma(q1, k1.y, f2fma(q0, k0.y, acc2[i][1]))));
        }
      }
#pragma unroll
      for (int i = 0; i < 8; i++) {
        u64* dst = (u64*)(sc + (r0 + i) * 136 + a0);
        dst[0] = acc2[i][0];
        dst[1] = acc2[i][1];
      }
    }

    // ---- phase A2: positional scores sp[ti][tj] = q_ti . pe[:, j0+tj] ----
    {
      u64 pacc2[4][2];
#pragma unroll
      for (int i = 0; i < 4; i++) { pacc2[i][0] = 0ull; pacc2[i][1] = 0ull; }
#pragma unroll 2
      for (int d = 0; d < 64; d += 4) {
        ulonglong2 p0 = *(const ulonglong2*)(pes + (d + 0) * 68 + tx0);
        ulonglong2 p1 = *(const ulonglong2*)(pes + (d + 1) * 68 + tx0);
        ulonglong2 p2 = *(const ulonglong2*)(pes + (d + 2) * 68 + tx0);
        ulonglong2 p3 = *(const ulonglong2*)(pes + (d + 3) * 68 + tx0);
#pragma unroll
        for (int i = 0; i < 4; i++) {
          float4 qa = *(const float4*)(qs + (ti0 + i) * 68 + d);
          u64 q0 = bc2(qa.x), q1 = bc2(qa.y), q2 = bc2(qa.z), q3 = bc2(qa.w);
          pacc2[i][0] = f2fma(q3, p3.x, f2fma(q2, p2.x, f2fma(q1, p1.x, f2fma(q0, p0.x, pacc2[i][0]))));
          pacc2[i][1] = f2fma(q3, p3.y, f2fma(q2, p2.y, f2fma(q1, p1.y, f2fma(q0, p0.y, pacc2[i][1]))));
        }
      }
#pragma unroll
      for (int i = 0; i < 4; i++) {
        u64* dst = (u64*)(sp + (ti0 + i) * 68 + tx0);
        dst[0] = pacc2[i][0];
        dst[1] = pacc2[i][1];
      }
    }
    __syncthreads();

    // ---- phase B: online softmax per row; probs back into sc (abs layout,
    //      complement zeroed); numerator masked, denominator unmasked ----
    {
      // span mask depends only on (j0, lane): hoisted out of the row loop
      const float m0 = fminf(fmaxf(((float)(j0 + lane) - 1023.0f + spanL) * 0.03125f + 1.0f, 0.f), 1.f);
      const float m1 = fminf(fmaxf(((float)(j0 + lane + 32) - 1023.0f + spanL) * 0.03125f + 1.0f, 0.f), 1.f);
      for (int rr = 0; rr < 8; rr++) {
        int ti = (w << 3) + rr;   // each warp owns rows 8w..8w+7 exclusively
        float* scr = sc + ti * 136;
        const float* spr = sp + ti * 68;
        float v0 = (scr[ti + lane] + spr[lane]) * SCALEF;
        float v1 = (scr[ti + lane + 32] + spr[lane + 32]) * SCALEF;
        float mx = fmaxf(v0, v1);
#pragma unroll
        for (int o = 16; o; o >>= 1) mx = fmaxf(mx, __shfl_xor_sync(0xffffffffu, mx, o));
        float mold = rm[ti];
        float mnew = fmaxf(mold, mx);
        float p0 = __expf(v0 - mnew), p1 = __expf(v1 - mnew);
        float s = p0 + p1;
#pragma unroll
        for (int o = 16; o; o >>= 1) s += __shfl_xor_sync(0xffffffffu, s, o);
        if (lane == 0) {
          float f = __expf(mold - mnew);
          rsum[ti] = rsum[ti] * f + s;
          rm[ti] = mnew;
          rc[ti] = f;
        }
        scr[ti + lane] = p0 * m0;
        scr[ti + lane + 32] = p1 * m1;
        scr[(ti + lane + 64) & 127] = 0.f;   // zero complement of the band
        scr[(ti + lane + 96) & 127] = 0.f;
      }
    }
    __syncthreads();

    // ---- phase C: out = out*rescale + probs_abs @ V_band (64x128x64) ----
    {
      u64 f0 = bc2(rc[ti0 + 0]), f1 = bc2(rc[ti0 + 1]);
      u64 f2v = bc2(rc[ti0 + 2]), f3 = bc2(rc[ti0 + 3]);
      out2[0][0] = f2mul(out2[0][0], f0); out2[0][1] = f2mul(out2[0][1], f0);
      out2[1][0] = f2mul(out2[1][0], f1); out2[1][1] = f2mul(out2[1][1], f1);
      out2[2][0] = f2mul(out2[2][0], f2v); out2[2][1] = f2mul(out2[2][1], f2v);
      out2[3][0] = f2mul(out2[3][0], f3); out2[3][1] = f2mul(out2[3][1], f3);
#pragma unroll 4
      for (int a = 0; a < 128; a += 2) {
        ulonglong2 va = *(const ulonglong2*)(vs + (a + 0) * 68 + tx0);
        ulonglong2 vb = *(const ulonglong2*)(vs + (a + 1) * 68 + tx0);
        float2 q0 = *(const float2*)(sc + (ti0 + 0) * 136 + a);
        float2 q1 = *(const float2*)(sc + (ti0 + 1) * 136 + a);
        float2 q2 = *(const float2*)(sc + (ti0 + 2) * 136 + a);
        float2 q3 = *(const float2*)(sc + (ti0 + 3) * 136 + a);
        u64 p00 = bc2(q0.x), p01 = bc2(q0.y);
        u64 p10 = bc2(q1.x), p11 = bc2(q1.y);
        u64 p20 = bc2(q2.x), p21 = bc2(q2.y);
        u64 p30 = bc2(q3.x), p31 = bc2(q3.y);
        out2[0][0] = f2fma(p01, vb.x, f2fma(p00, va.x, out2[0][0]));
        out2[0][1] = f2fma(p01, vb.y, f2fma(p00, va.y, out2[0][1]));
        out2[1][0] = f2fma(p11, vb.x, f2fma(p10, va.x, out2[1][0]));
        out2[1][1] = f2fma(p11, vb.y, f2fma(p10, va.y, out2[1][1]));
        out2[2][0] = f2fma(p21, vb.x, f2fma(p20, va.x, out2[2][0]));
        out2[2][1] = f2fma(p21, vb.y, f2fma(p20, va.y, out2[2][1]));
        out2[3][0] = f2fma(p31, vb.x, f2fma(p30, va.x, out2[3][0]));
        out2[3][1] = f2fma(p31, vb.y, f2fma(p30, va.y, out2[3][1]));
      }
    }
  }

  // epilogue: divide by unmasked softmax denominator, store head output
#pragma unroll
  for (int i = 0; i < 4; i++) {
    float inv = 1.0f / rsum[ti0 + i];
    float4 o;
    upk(out2[i][0], o.x, o.y);
    upk(out2[i][1], o.z, o.w);
    o.x *= inv; o.y *= inv; o.z *= inv; o.w *= inv;
    *(float4*)(AO + (size_t)(b * MQ + i0 + ti0 + i) * HID + hd * DHEAD + tx0) = o;
  }
}

extern "C" void kernel_launch(void* const* d_in, const int* in_sizes, int n_in,
                              void* d_out, int out_size) {
  const float* query = (const float*)d_in[0];
  const float* key = (const float*)d_in[1];
  const float* value = (const float*)d_in[2];
  const float* key_pe = (const float*)d_in[3];
  const float* Wq = (const float*)d_in[4];
  const float* Wk = (const float*)d_in[5];
  const float* Wv = (const float*)d_in[6];
  const float* Wo = (const float*)d_in[7];
  const float* span = (const float*)d_in[8];
  float* out = (float*)d_out;

  float *Qp, *Kp, *Vp, *AOp;
  cudaGetSymbolAddress((void**)&Qp, g_Q);
  cudaGetSymbolAddress((void**)&Kp, g_K);
  cudaGetSymbolAddress((void**)&Vp, g_V);
  cudaGetSymbolAddress((void**)&AOp, g_AO);

  cudaFuncSetAttribute(attn_kernel, cudaFuncAttributeMaxDynamicSharedMemorySize,
                       SM_BYTES);

  gemm_xwt<<<dim3(32, 8), 256>>>(query, Wq, Qp);      // Q proj  [4096,512]
  gemm_xwt<<<dim3(96, 8), 256>>>(key, Wk, Kp);        // K proj  [12288,512]
  gemm_xwt<<<dim3(96, 8), 256>>>(value, Wv, Vp);      // V proj  [12288,512]
  attn_kernel<<<dim3(8, 64), 256, SM_BYTES>>>(Qp, Kp, Vp, key_pe, span, AOp);
  gemm_xwt<<<dim3(32, 8), 256>>>(AOp, Wo, out);       // O proj  [4096,512]
}

// round 9
// speedup vs baseline: 1.2455x; 1.2455x over previous
#include <cuda_runtime.h>

#define HID 512
#define NHEAD 8
#define DHEAD 64
#define NB 8
#define MQ 512
#define LW 1024
#define SKV 1536
#define SCALEF 0.125f

typedef unsigned long long u64;

// ---- packed f32x2 helpers (sm_100+): one FFMA2 = 2 FMAs per issue slot ----
__device__ __forceinline__ u64 pk2(float lo, float hi) {
  u64 r; asm("mov.b64 %0, {%1, %2};" : "=l"(r) : "f"(lo), "f"(hi)); return r;
}
__device__ __forceinline__ u64 bc2(float x) { return pk2(x, x); }
__device__ __forceinline__ u64 f2fma(u64 a, u64 b, u64 c) {
  u64 d; asm("fma.rn.f32x2 %0, %1, %2, %3;" : "=l"(d) : "l"(a), "l"(b), "l"(c));
  return d;
}
__device__ __forceinline__ u64 f2mul(u64 a, u64 b) {
  u64 d; asm("mul.rn.f32x2 %0, %1, %2;" : "=l"(d) : "l"(a), "l"(b)); return d;
}
__device__ __forceinline__ void upk(u64 v, float& lo, float& hi) {
  asm("mov.b64 {%0, %1}, %2;" : "=f"(lo), "=f"(hi) : "l"(v));
}

// ---------------- scratch (device globals: allocation-free rule) -----------
__device__ float g_Q[NB * MQ * HID];     // 8 MB
__device__ float g_K[NB * SKV * HID];    // 24 MB
__device__ float g_V[NB * SKV * HID];    // 24 MB
__device__ float g_AO[NB * MQ * HID];    // 8 MB
__device__ float g_peT[LW * DHEAD];      // 256 KB: peT[j][d] = pe[d][j]

// ---------------- tiny transpose: pe[64][1024] -> peT[1024][64] ------------
__global__ __launch_bounds__(256) void transpose_pe(const float* __restrict__ pe,
                                                    float* __restrict__ peT) {
  __shared__ float tile[32][33];
  const int jt = blockIdx.x, dt = blockIdx.y;
  const int tx = threadIdx.x & 31, ty = threadIdx.x >> 5;
#pragma unroll
  for (int r = ty; r < 32; r += 8)
    tile[r][tx] = pe[(size_t)(dt * 32 + r) * LW + jt * 32 + tx];
  __syncthreads();
#pragma unroll
  for (int r = ty; r < 32; r += 8)
    peT[(size_t)(jt * 32 + r) * DHEAD + dt * 32 + tx] = tile[tx][r];
}

// ---------------- GEMM: Y[N,512] = X[N,512] @ W[512,512]^T -----------------
// 128x64 tile, BK=16, double-buffered smem (1 barrier/iter, LDG overlapped).
__global__ __launch_bounds__(256) void gemm_xwt(const float* __restrict__ X,
                                                const float* __restrict__ W,
                                                float* __restrict__ Y) {
  __shared__ __align__(16) float Xs[2][128][17];
  __shared__ __align__(16) float WsT[2][16][68];
  const int t = threadIdx.x;
  const int n0 = blockIdx.x << 7, o0 = blockIdx.y << 6;
  const int row0 = (t >> 4) << 3, col0 = (t & 15) << 2;
  const int lr = t >> 2, lc = (t & 3) << 2;

  u64 acc2[8][2];
#pragma unroll
  for (int i = 0; i < 8; i++) { acc2[i][0] = 0ull; acc2[i][1] = 0ull; }

  {  // prologue: k-tile 0 -> buffer 0
    float4 xa = *(const float4*)(X + (size_t)(n0 + lr) * HID + lc);
    float4 xb = *(const float4*)(X + (size_t)(n0 + lr + 64) * HID + lc);
    float4 wv = *(const float4*)(W + (size_t)(o0 + lr) * HID + lc);
    Xs[0][lr][lc + 0] = xa.x; Xs[0][lr][lc + 1] = xa.y;
    Xs[0][lr][lc + 2] = xa.z; Xs[0][lr][lc + 3] = xa.w;
    Xs[0][lr + 64][lc + 0] = xb.x; Xs[0][lr + 64][lc + 1] = xb.y;
    Xs[0][lr + 64][lc + 2] = xb.z; Xs[0][lr + 64][lc + 3] = xb.w;
    WsT[0][lc + 0][lr] = wv.x; WsT[0][lc + 1][lr] = wv.y;
    WsT[0][lc + 2][lr] = wv.z; WsT[0][lc + 3][lr] = wv.w;
  }
  int buf = 0;
  for (int h0 = 0; h0 < HID; h0 += 16) {
    __syncthreads();
    const bool more = (h0 + 16) < HID;
    float4 xa, xb, wv;
    if (more) {
      xa = *(const float4*)(X + (size_t)(n0 + lr) * HID + h0 + 16 + lc);
      xb = *(const float4*)(X + (size_t)(n0 + lr + 64) * HID + h0 + 16 + lc);
      wv = *(const float4*)(W + (size_t)(o0 + lr) * HID + h0 + 16 + lc);
    }
#pragma unroll
    for (int kk = 0; kk < 16; kk++) {
      const u64* b2 = (const u64*)(&WsT[buf][kk][col0]);
      u64 b0 = b2[0], b1 = b2[1];
#pragma unroll
      for (int i = 0; i < 8; i++) {
        u64 a2 = bc2(Xs[buf][row0 + i][kk]);
        acc2[i][0] = f2fma(a2, b0, acc2[i][0]);
        acc2[i][1] = f2fma(a2, b1, acc2[i][1]);
      }
    }
    if (more) {
      const int nb = buf ^ 1;
      Xs[nb][lr][lc + 0] = xa.x; Xs[nb][lr][lc + 1] = xa.y;
      Xs[nb][lr][lc + 2] = xa.z; Xs[nb][lr][lc + 3] = xa.w;
      Xs[nb][lr + 64][lc + 0] = xb.x; Xs[nb][lr + 64][lc + 1] = xb.y;
      Xs[nb][lr + 64][lc + 2] = xb.z; Xs[nb][lr + 64][lc + 3] = xb.w;
      WsT[nb][lc + 0][lr] = wv.x; WsT[nb][lc + 1][lr] = wv.y;
      WsT[nb][lc + 2][lr] = wv.z; WsT[nb][lc + 3][lr] = wv.w;
    }
    buf ^= 1;
  }
#pragma unroll
  for (int i = 0; i < 8; i++) {
    float4 v;
    upk(acc2[i][0], v.x, v.y);
    upk(acc2[i][1], v.z, v.w);
    *(float4*)(Y + (size_t)(n0 + row0 + i) * HID + o0 + col0) = v;
  }
}

// ---------------- fused sliding-window attention (transposed scores) -------
// Block = one (batch,head) x 64 queries. K/V band in a 128-slot ring
// (slot = rel_row & 127; 64 new rows per chunk, register-prefetched a chunk
// ahead). Scores TRANSPOSED: sct[slot][ti] = k_slot . q_ti, so K needs no
// per-chunk transpose (q transposed once per CTA). Softmax per ti down sct
// columns, probs in place (complement zeroed), AV consumes transposed probs.
// Mask post-softmax: masked numerator, unmasked denominator.
#define OFF_QST 0        /* [64][68]  qst[d][ti] */
#define OFF_PEST 4352    /* [64][68]  pest[tj][d] */
#define OFF_KB 8704      /* [128][68] K ring, row-major */
#define OFF_VB 17408     /* [128][68] V ring */
#define OFF_SCT 26112    /* [128][68] scores/probs transposed */
#define OFF_SPT 34816    /* [64][68]  spt[tj][ti] */
#define OFF_RM 39168
#define OFF_RSUM 39232
#define OFF_RC 39296
#define SM_FLOATS 39360
#define SM_BYTES (SM_FLOATS * 4)

__global__ __launch_bounds__(256, 1) void attn_kernel(
    const float* __restrict__ Q, const float* __restrict__ Kg,
    const float* __restrict__ Vg, const float* __restrict__ peT,
    const float* __restrict__ span, float* __restrict__ AO) {
  extern __shared__ __align__(16) float sm[];
  float* qst = sm + OFF_QST;
  float* pest = sm + OFF_PEST;
  float* kb = sm + OFF_KB;
  float* vb = sm + OFF_VB;
  float* sct = sm + OFF_SCT;
  float* spt = sm + OFF_SPT;
  float* rm = sm + OFF_RM;
  float* rsum = sm + OFF_RSUM;
  float* rc = sm + OFF_RC;

  const int t = threadIdx.x;
  const int w = t >> 5, l = t & 31;
  const int bh = blockIdx.y;
  const int b = bh >> 3, hd = bh & 7;
  const int i0 = blockIdx.x << 6;
  const float spanL = span[hd] * (float)LW;

  const float* Qb = Q + (size_t)(b * MQ + i0) * HID + hd * DHEAD;
  const float* K0 = Kg + (size_t)b * SKV * HID + hd * DHEAD + (size_t)i0 * HID;
  const float* V0 = Vg + (size_t)b * SKV * HID + hd * DHEAD + (size_t)i0 * HID;

  // q tile transposed once: qst[d][ti] (conflicted scalar stores, amortized)
#pragma unroll
  for (int it = 0; it < 4; it++) {
    int idx = t + (it << 8);
    int r = idx >> 4, c = (idx & 15) << 2;
    float4 v = *(const float4*)(Qb + (size_t)r * HID + c);
    qst[(c + 0) * 68 + r] = v.x;
    qst[(c + 1) * 68 + r] = v.y;
    qst[(c + 2) * 68 + r] = v.z;
    qst[(c + 3) * 68 + r] = v.w;
  }
  if (t < 64) { rm[t] = -3.0e38f; rsum[t] = 0.f; }

  // prologue: rel rows 0..127 -> slots 0..127 (row-major, no transpose)
#pragma unroll
  for (int it = 0; it < 8; it++) {
    int idx = t + (it << 8);
    int r = idx >> 4, c = (idx & 15) << 2;
    *(float4*)(kb + r * 68 + c) = *(const float4*)(K0 + (size_t)r * HID + c);
    *(float4*)(vb + r * 68 + c) = *(const float4*)(V0 + (size_t)r * HID + c);
  }

  // thread mappings
  const int h = l >> 4;
  const int sA1 = (w << 4) + (h << 3);  // A1: slots sA1..sA1+7
  const int tiv = (l & 15) << 2;        // A1/A2 ti vector group
  const int tjA2 = (w << 3) + (h << 2); // A2: tj rows tjA2..tjA2+3
  const int tiB = (w << 3) + (l & 7);   // B: owned query row
  const int partB = l >> 3;             // B: tj quarter (4 lanes per ti)
  const int ti0 = (t >> 4) << 2;        // C/epilogue: 4 query rows
  const int dv0 = (t & 15) << 2;        // C/epilogue: 4 head-dims

  u64 outa[4][2];
#pragma unroll
  for (int i = 0; i < 4; i++) { outa[i][0] = 0ull; outa[i][1] = 0ull; }

  float4 pfk[4], pfv[4];

  for (int ch = 0; ch < 16; ch++) {
    const int j0 = ch << 6;
    __syncthreads();  // prev chunk's readers done before ring/pe overwrite

    if (ch > 0) {  // store prefetched rows j0+64..j0+127 into their slots
      const int sbase = ((ch + 1) & 1) << 6;
#pragma unroll
      for (int it = 0; it < 4; it++) {
        int idx = t + (it << 8);
        int r = idx >> 4, c = (idx & 15) << 2;
        *(float4*)(kb + (sbase + r) * 68 + c) = pfk[it];
        *(float4*)(vb + (sbase + r) * 68 + c) = pfv[it];
      }
    }
    // stage pe chunk: pest[tj][d] = peT[j0+tj][d] (conflict-free)
#pragma unroll
    for (int it = 0; it < 4; it++) {
      int idx = t + (it << 8);
      int tj = idx >> 4, c = (idx & 15) << 2;
      *(float4*)(pest + tj * 68 + c) =
          *(const float4*)(peT + (size_t)(j0 + tj) * DHEAD + c);
    }
    __syncthreads();

    // register-prefetch next chunk's 64 new rows (latency hides under A1/A2)
    if (ch < 15) {
      const float* Kn = K0 + (size_t)(j0 + 128) * HID;
      const float* Vn = V0 + (size_t)(j0 + 128) * HID;
#pragma unroll
      for (int it = 0; it < 4; it++) {
        int idx = t + (it << 8);
        int r = idx >> 4, c = (idx & 15) << 2;
        pfk[it] = *(const float4*)(Kn + (size_t)r * HID + c);
        pfv[it] = *(const float4*)(Vn + (size_t)r * HID + c);
      }
    }

    // ---- A1: sct[slot][ti] = k_slot . q_ti (128x64; K broadcast reads) ----
    {
      u64 acc[8][2];
#pragma unroll
      for (int i = 0; i < 8; i++) { acc[i][0] = 0ull; acc[i][1] = 0ull; }
#pragma unroll 2
      for (int d = 0; d < 64; d += 4) {
        ulonglong2 q0 = *(const ulonglong2*)(qst + (d + 0) * 68 + tiv);
        ulonglong2 q1 = *(const ulonglong2*)(qst + (d + 1) * 68 + tiv);
        ulonglong2 q2 = *(const ulonglong2*)(qst + (d + 2) * 68 + tiv);
        ulonglong2 q3 = *(const ulonglong2*)(qst + (d + 3) * 68 + tiv);
#pragma unroll
        for (int i = 0; i < 8; i++) {
          float4 ka = *(const float4*)(kb + (sA1 + i) * 68 + d);
          u64 k0 = bc2(ka.x), k1 = bc2(ka.y), k2 = bc2(ka.z), k3 = bc2(ka.w);
          acc[i][0] = f2fma(k3, q3.x, f2fma(k2, q2.x, f2fma(k1, q1.x, f2fma(k0, q0.x, acc[i][0]))));
          acc[i][1] = f2fma(k3, q3.y, f2fma(k2, q2.y, f2fma(k1, q1.y, f2fma(k0, q0.y, acc[i][1]))));
        }
      }
#pragma unroll
      for (int i = 0; i < 8; i++) {
        ulonglong2 st; st.x = acc[i][0]; st.y = acc[i][1];
        *(ulonglong2*)(sct + (sA1 + i) * 68 + tiv) = st;
      }
    }

    // ---- A2: spt[tj][ti] = pe[:, j0+tj] . q_ti (64x64) ----
    {
      u64 acc[4][2];
#pragma unroll
      for (int i = 0; i < 4; i++) { acc[i][0] = 0ull; acc[i][1] = 0ull; }
#pragma unroll 2
      for (int d = 0; d < 64; d += 4) {
        ulonglong2 q0 = *(const ulonglong2*)(qst + (d + 0) * 68 + tiv);
        ulonglong2 q1 = *(const ulonglong2*)(qst + (d + 1) * 68 + tiv);
        ulonglong2 q2 = *(const ulonglong2*)(qst + (d + 2) * 68 + tiv);
        ulonglong2 q3 = *(const ulonglong2*)(qst + (d + 3) * 68 + tiv);
#pragma unroll
        for (int i = 0; i < 4; i++) {
          float4 pa = *(const float4*)(pest + (tjA2 + i) * 68 + d);
          u64 p0 = bc2(pa.x), p1 = bc2(pa.y), p2 = bc2(pa.z), p3 = bc2(pa.w);
          acc[i][0] = f2fma(p3, q3.x, f2fma(p2, q2.x, f2fma(p1, q1.x, f2fma(p0, q0.x, acc[i][0]))));
          acc[i][1] = f2fma(p3, q3.y, f2fma(p2, q2.y, f2fma(p1, q1.y, f2fma(p0, q0.y, acc[i][1]))));
        }
      }
#pragma unroll
      for (int i = 0; i < 4; i++) {
        ulonglong2 st; st.x = acc[i][0]; st.y = acc[i][1];
        *(ulonglong2*)(spt + (tjA2 + i) * 68 + tiv) = st;
      }
    }
    __syncthreads();

    // ---- B: online softmax per ti (4 lanes/ti), probs in place ----
    {
      float vv[16];
#pragma unroll
      for (int i = 0; i < 16; i++) {
        int tjl = (partB << 4) + i;
        int slot = (tiB + tjl + j0) & 127;
        vv[i] = (sct[slot * 68 + tiB] + spt[tjl * 68 + tiB]) * SCALEF;
      }
      float mx = vv[0];
#pragma unroll
      for (int i = 1; i < 16; i++) mx = fmaxf(mx, vv[i]);
      mx = fmaxf(mx, __shfl_xor_sync(0xffffffffu, mx, 8));
      mx = fmaxf(mx, __shfl_xor_sync(0xffffffffu, mx, 16));
      float mold = rm[tiB];
      float mnew = fmaxf(mold, mx);
      float s = 0.f;
      float pv[16];
#pragma unroll
      for (int i = 0; i < 16; i++) { pv[i] = __expf(vv[i] - mnew); s += pv[i]; }
      s += __shfl_xor_sync(0xffffffffu, s, 8);
      s += __shfl_xor_sync(0xffffffffu, s, 16);
      if (l < 8) {
        float f = __expf(mold - mnew);
        rm[tiB] = mnew; rsum[tiB] = rsum[tiB] * f + s; rc[tiB] = f;
      }
#pragma unroll
      for (int i = 0; i < 16; i++) {
        int tjl = (partB << 4) + i;
        float msk = fminf(
            fmaxf(((float)(j0 + tjl) - 1023.0f + spanL) * 0.03125f + 1.0f, 0.f),
            1.f);
        int slot = (tiB + tjl + j0) & 127;
        sct[slot * 68 + tiB] = pv[i] * msk;  // masked numerator
      }
#pragma unroll
      for (int i = 0; i < 16; i++) {  // zero the 64-slot complement
        int z = (partB << 4) + i;
        int slot = (tiB + 64 + z + j0) & 127;
        sct[slot * 68 + tiB] = 0.f;
      }
    }
    __syncthreads();

    // ---- C: out = out*rescale + probs^T @ V (all 128 slots, 4ti x 4dv) ----
    {
#pragma unroll
      for (int i = 0; i < 4; i++) {
        u64 fb = bc2(rc[ti0 + i]);
        outa[i][0] = f2mul(outa[i][0], fb);
        outa[i][1] = f2mul(outa[i][1], fb);
      }
#pragma unroll 4
      for (int s = 0; s < 128; s++) {
        ulonglong2 vv = *(const ulonglong2*)(vb + s * 68 + dv0);
        float4 pa = *(const float4*)(sct + s * 68 + ti0);  // broadcast
        u64 p;
        p = bc2(pa.x); outa[0][0] = f2fma(p, vv.x, outa[0][0]); outa[0][1] = f2fma(p, vv.y, outa[0][1]);
        p = bc2(pa.y); outa[1][0] = f2fma(p, vv.x, outa[1][0]); outa[1][1] = f2fma(p, vv.y, outa[1][1]);
        p = bc2(pa.z); outa[2][0] = f2fma(p, vv.x, outa[2][0]); outa[2][1] = f2fma(p, vv.y, outa[2][1]);
        p = bc2(pa.w); outa[3][0] = f2fma(p, vv.x, outa[3][0]); outa[3][1] = f2fma(p, vv.y, outa[3][1]);
      }
    }
  }

  // epilogue: divide by unmasked denominator, store head output
#pragma unroll
  for (int i = 0; i < 4; i++) {
    float inv = 1.0f / rsum[ti0 + i];
    float4 o;
    upk(outa[i][0], o.x, o.y);
    upk(outa[i][1], o.z, o.w);
    o.x *= inv; o.y *= inv; o.z *= inv; o.w *= inv;
    *(float4*)(AO + (size_t)(b * MQ + i0 + ti0 + i) * HID + hd * DHEAD + dv0) = o;
  }
}

extern "C" void kernel_launch(void* const* d_in, const int* in_sizes, int n_in,
                              void* d_out, int out_size) {
  const float* query = (const float*)d_in[0];
  const float* key = (const float*)d_in[1];
  const float* value = (const float*)d_in[2];
  const float* key_pe = (const float*)d_in[3];
  const float* Wq = (const float*)d_in[4];
  const float* Wk = (const float*)d_in[5];
  const float* Wv = (const float*)d_in[6];
  const float* Wo = (const float*)d_in[7];
  const float* span = (const float*)d_in[8];
  float* out = (float*)d_out;

  float *Qp, *Kp, *Vp, *AOp, *peTp;
  cudaGetSymbolAddress((void**)&Qp, g_Q);
  cudaGetSymbolAddress((void**)&Kp, g_K);
  cudaGetSymbolAddress((void**)&Vp, g_V);
  cudaGetSymbolAddress((void**)&AOp, g_AO);
  cudaGetSymbolAddress((void**)&peTp, g_peT);

  cudaFuncSetAttribute(attn_kernel, cudaFuncAttributeMaxDynamicSharedMemorySize,
                       SM_BYTES);

  transpose_pe<<<dim3(32, 2), 256>>>(key_pe, peTp);
  gemm_xwt<<<dim3(32, 8), 256>>>(query, Wq, Qp);      // Q proj  [4096,512]
  gemm_xwt<<<dim3(96, 8), 256>>>(key, Wk, Kp);        // K proj  [12288,512]
  gemm_xwt<<<dim3(96, 8), 256>>>(value, Wv, Vp);      // V proj  [12288,512]
  attn_kernel<<<dim3(8, 64), 256, SM_BYTES>>>(Qp, Kp, Vp, peTp, span, AOp);
  gemm_xwt<<<dim3(32, 8), 256>>>(AOp, Wo, out);       // O proj  [4096,512]
}